// round 11
// baseline (speedup 1.0000x reference)
#include <cuda_runtime.h>
#include <cuda_bf16.h>

// MSDeformAttn on GB300 (sm_103a) — float4 gather + smem-staged setup + deep batch
//   B=2, Hd=8, C=32, P=4, levels=4
//   SHAPES = [(100,150),(50,75),(25,38),(13,19)], L = Q = 19947
//
// Calibrated across R1-R9: runtime = L1 wavefront work / achieved L1%.
//   - float4 shape (4 groups x 8 lanes): lowest L1 work (~96us-equiv) but ran
//     at only ~70% L1 when loads were shallowly interleaved (R4).
//   - smem-staged setup + 8-deep load batching reached 86% L1 (R9) but on the
//     costlier LDG.64 shape.
// This kernel = float4 shape + staged setup + full-level load batching.
// Each thread handles ONE point per level -> only 8 LDS.128/thread of staged
// setup + 16 gather LDG.128. Out-of-bounds corners zeroed through weights
// (reference clip+mask semantics); corner indices pre-clamped.

#define QTOT 19947
#define LTOT 19947
#define HD   8
#define CH   32
#define ROWF4 (HD * CH / 4)   // float4 stride between spatial positions = 64

__global__ void __launch_bounds__(256, 8)
msda_kernel(const float* __restrict__ value,
            const float* __restrict__ loc,
            const float* __restrict__ attw,
            float* __restrict__ out)
{
    __shared__ float4 sw[8][16];   // folded bilinear weights per (warp, l*4+p)
    __shared__ int4   sr[8][16];   // clamped corner offsets (float4 units, incl. level start)

    const int warp = threadIdx.x >> 5;
    const int lane = threadIdx.x & 31;
    const int q = blockIdx.x * 8 + warp;
    if (q >= QTOT) return;                 // uniform across warp

    const int bh = blockIdx.y;             // b*8 + h
    const int b  = bh >> 3;
    const int h  = bh & 7;
    const int qbh = (b * QTOT + q) * HD + h;

    // ---- phase 1: lanes 0-15 compute one (level,point) each ----
    if (lane < 16) {
        const int l = lane >> 2;
        const int Hh = (l == 0) ? 100 : (l == 1) ? 50 : (l == 2) ? 25 : 13;
        const int Ww = (l == 0) ? 150 : (l == 1) ? 75 : (l == 2) ? 38 : 19;
        const int S  = (l == 0) ? 0   : (l == 1) ? 15000 : (l == 2) ? 18750 : 19700;

        const float2 xy = ((const float2*)loc)[(size_t)qbh * 16 + lane]; // coalesced 128B
        const float  wt = attw[(size_t)qbh * 16 + lane];                 // coalesced 64B

        const float x = xy.x * (float)Ww - 0.5f;
        const float y = xy.y * (float)Hh - 0.5f;
        const float xf = floorf(x);
        const float yf = floorf(y);
        const float dx = x - xf;
        const float dy = y - yf;
        const int x0 = (int)xf;            // in [-1, Ww-1]
        const int y0 = (int)yf;            // in [-1, Hh-1]

        const float fx0 = ((unsigned)x0       < (unsigned)Ww) ? 1.f : 0.f;
        const float fx1 = ((unsigned)(x0 + 1) < (unsigned)Ww) ? 1.f : 0.f;
        const float fy0 = ((unsigned)y0       < (unsigned)Hh) ? 1.f : 0.f;
        const float fy1 = ((unsigned)(y0 + 1) < (unsigned)Hh) ? 1.f : 0.f;

        const float gy0 = wt * (1.f - dy) * fy0;
        const float gy1 = wt * dy * fy1;
        const float gx0 = (1.f - dx) * fx0;
        const float gx1 = dx * fx1;

        sw[warp][lane] = make_float4(gy0 * gx0, gy0 * gx1, gy1 * gx0, gy1 * gx1);

        const int x0c = max(x0, 0);
        const int x1c = min(x0 + 1, Ww - 1);
        const int y0c = max(y0, 0);
        const int y1c = min(y0 + 1, Hh - 1);
        const int row0 = S + y0c * Ww;
        const int row1 = S + y1c * Ww;
        sr[warp][lane] = make_int4((row0 + x0c) * ROWF4, (row0 + x1c) * ROWF4,
                                   (row1 + x0c) * ROWF4, (row1 + x1c) * ROWF4);
    }
    __syncwarp();

    // ---- phase 2: gather (4 groups x 8 lanes x float4; point = group) ----
    const int group = lane >> 3;           // point index within each level
    const int sub   = lane & 7;            // channel quad

    const float4* vbase = (const float4*)(value + ((size_t)b * LTOT) * (HD * CH)
                                                + (size_t)h * CH) + sub;

    float4 acc = make_float4(0.f, 0.f, 0.f, 0.f);

#pragma unroll
    for (int l = 0; l < 4; ++l) {
        const int ip = l * 4 + group;

        // offsets first, then ALL 4 corner loads back-to-back (MLP=4; levels
        // are mutually independent so ptxas can overlap further)
        const int4 r = sr[warp][ip];       // broadcast LDS.128

        const float4 va = vbase[r.x];
        const float4 vb = vbase[r.y];
        const float4 vc = vbase[r.z];
        const float4 vd = vbase[r.w];

        const float4 w = sw[warp][ip];     // broadcast LDS.128 (after loads issued)

        acc.x += w.x * va.x; acc.y += w.x * va.y; acc.z += w.x * va.z; acc.w += w.x * va.w;
        acc.x += w.y * vb.x; acc.y += w.y * vb.y; acc.z += w.y * vb.z; acc.w += w.y * vb.w;
        acc.x += w.z * vc.x; acc.y += w.z * vc.y; acc.z += w.z * vc.z; acc.w += w.z * vc.w;
        acc.x += w.w * vd.x; acc.y += w.w * vd.y; acc.z += w.w * vd.z; acc.w += w.w * vd.w;
    }

    // ---- reduce the 4 point-groups (lanes s, s+8, s+16, s+24) ----
    acc.x += __shfl_xor_sync(0xffffffffu, acc.x, 8);
    acc.y += __shfl_xor_sync(0xffffffffu, acc.y, 8);
    acc.z += __shfl_xor_sync(0xffffffffu, acc.z, 8);
    acc.w += __shfl_xor_sync(0xffffffffu, acc.w, 8);
    acc.x += __shfl_xor_sync(0xffffffffu, acc.x, 16);
    acc.y += __shfl_xor_sync(0xffffffffu, acc.y, 16);
    acc.z += __shfl_xor_sync(0xffffffffu, acc.z, 16);
    acc.w += __shfl_xor_sync(0xffffffffu, acc.w, 16);

    if (group == 0) {
        // out[b, q, h*32 + 4*sub .. +4) : 8 lanes x 16B = one 128B store
        *(float4*)(out + (size_t)qbh * CH + sub * 4) = acc;
    }
}

extern "C" void kernel_launch(void* const* d_in, const int* in_sizes, int n_in,
                              void* d_out, int out_size)
{
    const float* value = (const float*)d_in[0];
    const float* loc   = (const float*)d_in[3];
    const float* attw  = (const float*)d_in[4];
    float* out = (float*)d_out;

    dim3 grid((QTOT + 7) / 8, 2 * HD, 1);
    msda_kernel<<<grid, 256>>>(value, loc, attw, out);
}

// round 14
// speedup vs baseline: 1.0089x; 1.0089x over previous
#include <cuda_runtime.h>
#include <cuda_bf16.h>

// MSDeformAttn on GB300 (sm_103a) — warp-per-corner gather (1 line per LDG)
//   B=2, Hd=8, C=32, P=4, levels=4
//   SHAPES = [(100,150),(50,75),(25,38),(13,19)], L = Q = 19947
//
// Every prior shape paid L1tex within-LDG replay (2.07 cyc/extra line): the
// gather LDGs touched 2 or 4 distinct 128B lines each. Here one corner's
// 128B line (= all 32 channels of one head) is loaded by the WHOLE warp as
// 32 LDG.32 lanes: exactly 1 line, 1 wavefront, zero replays. A warp walks
// 16 points x 4 corners = 64 such loads. Each lane owns one channel, so the
// cross-lane reduction disappears entirely and the output is a single
// coalesced STG.32 per lane.
// Per-point setup (folded bilinear weights + clamped corner offsets) is
// computed once by lanes 0-15 and staged in smem (R9-proven structure).
// Out-of-bounds corners are zeroed through the weights (reference clip+mask
// semantics); indices pre-clamped.

#define QTOT 19947
#define LTOT 19947
#define HD   8
#define CH   32
#define ROWF (HD * CH)        // floats between spatial positions = 256

__global__ void __launch_bounds__(256, 8)
msda_kernel(const float* __restrict__ value,
            const float* __restrict__ loc,
            const float* __restrict__ attw,
            float* __restrict__ out)
{
    __shared__ float4 sw[8][16];   // folded bilinear weights per (warp, l*4+p)
    __shared__ int4   sr[8][16];   // clamped corner offsets in FLOAT units (incl. level start)

    const int warp = threadIdx.x >> 5;
    const int lane = threadIdx.x & 31;
    const int q = blockIdx.x * 8 + warp;
    if (q >= QTOT) return;                 // uniform across warp

    const int bh = blockIdx.y;             // b*8 + h
    const int b  = bh >> 3;
    const int h  = bh & 7;
    const int qbh = (b * QTOT + q) * HD + h;

    // ---- phase 1: lanes 0-15 compute one (level,point) each ----
    if (lane < 16) {
        const int l = lane >> 2;
        const int Hh = (l == 0) ? 100 : (l == 1) ? 50 : (l == 2) ? 25 : 13;
        const int Ww = (l == 0) ? 150 : (l == 1) ? 75 : (l == 2) ? 38 : 19;
        const int S  = (l == 0) ? 0   : (l == 1) ? 15000 : (l == 2) ? 18750 : 19700;

        const float2 xy = ((const float2*)loc)[(size_t)qbh * 16 + lane]; // coalesced 128B
        const float  wt = attw[(size_t)qbh * 16 + lane];                 // coalesced 64B

        const float x = xy.x * (float)Ww - 0.5f;
        const float y = xy.y * (float)Hh - 0.5f;
        const float xf = floorf(x);
        const float yf = floorf(y);
        const float dx = x - xf;
        const float dy = y - yf;
        const int x0 = (int)xf;            // in [-1, Ww-1]
        const int y0 = (int)yf;            // in [-1, Hh-1]

        const float fx0 = ((unsigned)x0       < (unsigned)Ww) ? 1.f : 0.f;
        const float fx1 = ((unsigned)(x0 + 1) < (unsigned)Ww) ? 1.f : 0.f;
        const float fy0 = ((unsigned)y0       < (unsigned)Hh) ? 1.f : 0.f;
        const float fy1 = ((unsigned)(y0 + 1) < (unsigned)Hh) ? 1.f : 0.f;

        const float gy0 = wt * (1.f - dy) * fy0;
        const float gy1 = wt * dy * fy1;
        const float gx0 = (1.f - dx) * fx0;
        const float gx1 = dx * fx1;

        sw[warp][lane] = make_float4(gy0 * gx0, gy0 * gx1, gy1 * gx0, gy1 * gx1);

        const int x0c = max(x0, 0);
        const int x1c = min(x0 + 1, Ww - 1);
        const int y0c = max(y0, 0);
        const int y1c = min(y0 + 1, Hh - 1);
        const int row0 = S + y0c * Ww;
        const int row1 = S + y1c * Ww;
        sr[warp][lane] = make_int4((row0 + x0c) * ROWF, (row0 + x1c) * ROWF,
                                   (row1 + x0c) * ROWF, (row1 + x1c) * ROWF);
    }
    __syncwarp();

    // ---- phase 2: whole warp loads each corner's full line (lane = channel) ----
    const float* vbase = value + ((size_t)b * LTOT) * ROWF + h * CH + lane;

    float acc = 0.f;

#pragma unroll
    for (int p = 0; p < 16; ++p) {
        const int4   r = sr[warp][p];      // broadcast LDS.128
        const float4 w = sw[warp][p];      // broadcast LDS.128

        // 4 corner loads, each exactly one 128B line for the warp
        const float v0 = vbase[r.x];
        const float v1 = vbase[r.y];
        const float v2 = vbase[r.z];
        const float v3 = vbase[r.w];

        acc += w.x * v0;
        acc += w.y * v1;
        acc += w.z * v2;
        acc += w.w * v3;
    }

    // lane owns channel `lane`: out[b, q, h*32 + lane]; 32 lanes = one 128B store
    out[(size_t)qbh * CH + lane] = acc;
}

extern "C" void kernel_launch(void* const* d_in, const int* in_sizes, int n_in,
                              void* d_out, int out_size)
{
    const float* value = (const float*)d_in[0];
    const float* loc   = (const float*)d_in[3];
    const float* attw  = (const float*)d_in[4];
    float* out = (float*)d_out;

    dim3 grid((QTOT + 7) / 8, 2 * HD, 1);
    msda_kernel<<<grid, 256>>>(value, loc, attw, out);
}

// round 15
// speedup vs baseline: 1.0698x; 1.0604x over previous
#include <cuda_runtime.h>
#include <cuda_bf16.h>

// MSDeformAttn on GB300 (sm_103a) — 2 queries/warp, float4 gather, staged setup
//   B=2, Hd=8, C=32, P=4, levels=4
//   SHAPES = [(100,150),(50,75),(25,38),(13,19)], L = Q = 19947
//
// Measured across R1-R13: l1tex busy-work scales with gather-LDG instruction
// count (96/123/145 us-equiv for 16/32/64 instr per query), so the float4
// shape (4 groups x 8 lanes, 16 LDG.128) is minimum-work; its 137us plateau
// was ~69% utilization from shallow (<=2) load interleave. This version runs
// TWO independent queries per warp: per level, 8 gather loads (4 per query)
// issue back-to-back from two independent chains before any consume, keeping
// ~8+ lines continuously in flight per warp. 40 warps/SM x 8 = 320 in-flight
// lines >= L2 latency -> l1tex saturation predicted despite 62% occupancy.
// Setup (folded bilinear weights + pre-clamped corner offsets) is computed
// once by all 32 lanes (16 per query) and staged in smem. Out-of-bounds
// corners zeroed through weights (reference clip+mask semantics).

#define QTOT 19947
#define LTOT 19947
#define HD   8
#define CH   32
#define ROWF4 (HD * CH / 4)   // float4 stride between spatial positions = 64

__global__ void __launch_bounds__(256, 5)
msda_kernel(const float* __restrict__ value,
            const float* __restrict__ loc,
            const float* __restrict__ attw,
            float* __restrict__ out)
{
    __shared__ float4 sw[8][2][16];   // [warp][query][l*4+p] folded weights
    __shared__ int4   sr[8][2][16];   // [warp][query][l*4+p] clamped offsets (float4 units)

    const int warp = threadIdx.x >> 5;
    const int lane = threadIdx.x & 31;

    const int q0 = blockIdx.x * 16 + warp * 2;   // this warp's first query
    if (q0 >= QTOT) return;                      // uniform across warp
    const bool q1ok = (q0 + 1) < QTOT;
    const int q1 = q1ok ? (q0 + 1) : q0;         // clamp (compute-only duplicate)

    const int bh = blockIdx.y;                   // b*8 + h
    const int b  = bh >> 3;
    const int h  = bh & 7;
    const int qbh0 = (b * QTOT + q0) * HD + h;
    const int qbh1 = (b * QTOT + q1) * HD + h;

    // ---- phase 1: all 32 lanes; lane<16 -> q0 points, lane>=16 -> q1 points ----
    {
        const int qs  = lane >> 4;               // query select
        const int idx = lane & 15;               // l*4+p
        const int l = idx >> 2;
        const int Hh = (l == 0) ? 100 : (l == 1) ? 50 : (l == 2) ? 25 : 13;
        const int Ww = (l == 0) ? 150 : (l == 1) ? 75 : (l == 2) ? 38 : 19;
        const int S  = (l == 0) ? 0   : (l == 1) ? 15000 : (l == 2) ? 18750 : 19700;

        const int qbh = qs ? qbh1 : qbh0;
        const float2 xy = ((const float2*)loc)[(size_t)qbh * 16 + idx]; // 2x128B / warp
        const float  wt = attw[(size_t)qbh * 16 + idx];                 // 2x64B / warp

        const float x = xy.x * (float)Ww - 0.5f;
        const float y = xy.y * (float)Hh - 0.5f;
        const float xf = floorf(x);
        const float yf = floorf(y);
        const float dx = x - xf;
        const float dy = y - yf;
        const int x0 = (int)xf;                  // in [-1, Ww-1]
        const int y0 = (int)yf;                  // in [-1, Hh-1]

        const float fx0 = ((unsigned)x0       < (unsigned)Ww) ? 1.f : 0.f;
        const float fx1 = ((unsigned)(x0 + 1) < (unsigned)Ww) ? 1.f : 0.f;
        const float fy0 = ((unsigned)y0       < (unsigned)Hh) ? 1.f : 0.f;
        const float fy1 = ((unsigned)(y0 + 1) < (unsigned)Hh) ? 1.f : 0.f;

        const float gy0 = wt * (1.f - dy) * fy0;
        const float gy1 = wt * dy * fy1;
        const float gx0 = (1.f - dx) * fx0;
        const float gx1 = dx * fx1;

        sw[warp][qs][idx] = make_float4(gy0 * gx0, gy0 * gx1, gy1 * gx0, gy1 * gx1);

        const int x0c = max(x0, 0);
        const int x1c = min(x0 + 1, Ww - 1);
        const int y0c = max(y0, 0);
        const int y1c = min(y0 + 1, Hh - 1);
        const int row0 = S + y0c * Ww;
        const int row1 = S + y1c * Ww;
        sr[warp][qs][idx] = make_int4((row0 + x0c) * ROWF4, (row0 + x1c) * ROWF4,
                                      (row1 + x0c) * ROWF4, (row1 + x1c) * ROWF4);
    }
    __syncwarp();

    // ---- phase 2: gather, 4 groups x 8 lanes x float4; 2 chains per warp ----
    const int group = lane >> 3;                 // point index within each level
    const int sub   = lane & 7;                  // channel quad

    const float4* vbase = (const float4*)(value + ((size_t)b * LTOT) * (HD * CH)
                                                + (size_t)h * CH) + sub;

    float4 acc0 = make_float4(0.f, 0.f, 0.f, 0.f);
    float4 acc1 = make_float4(0.f, 0.f, 0.f, 0.f);

#pragma unroll
    for (int l = 0; l < 4; ++l) {
        const int ip = l * 4 + group;

        const int4 r0 = sr[warp][0][ip];         // broadcast LDS.128
        const int4 r1 = sr[warp][1][ip];         // broadcast LDS.128

        // 8 independent gather loads back-to-back (two query chains)
        const float4 a0 = vbase[r0.x];
        const float4 a1 = vbase[r0.y];
        const float4 a2 = vbase[r0.z];
        const float4 a3 = vbase[r0.w];
        const float4 b0 = vbase[r1.x];
        const float4 b1 = vbase[r1.y];
        const float4 b2 = vbase[r1.z];
        const float4 b3 = vbase[r1.w];

        const float4 w0 = sw[warp][0][ip];
        const float4 w1 = sw[warp][1][ip];

        acc0.x += w0.x * a0.x; acc0.y += w0.x * a0.y; acc0.z += w0.x * a0.z; acc0.w += w0.x * a0.w;
        acc0.x += w0.y * a1.x; acc0.y += w0.y * a1.y; acc0.z += w0.y * a1.z; acc0.w += w0.y * a1.w;
        acc0.x += w0.z * a2.x; acc0.y += w0.z * a2.y; acc0.z += w0.z * a2.z; acc0.w += w0.z * a2.w;
        acc0.x += w0.w * a3.x; acc0.y += w0.w * a3.y; acc0.z += w0.w * a3.z; acc0.w += w0.w * a3.w;

        acc1.x += w1.x * b0.x; acc1.y += w1.x * b0.y; acc1.z += w1.x * b0.z; acc1.w += w1.x * b0.w;
        acc1.x += w1.y * b1.x; acc1.y += w1.y * b1.y; acc1.z += w1.y * b1.z; acc1.w += w1.y * b1.w;
        acc1.x += w1.z * b2.x; acc1.y += w1.z * b2.y; acc1.z += w1.z * b2.z; acc1.w += w1.z * b2.w;
        acc1.x += w1.w * b3.x; acc1.y += w1.w * b3.y; acc1.z += w1.w * b3.z; acc1.w += w1.w * b3.w;
    }

    // ---- reduce the 4 point-groups for both queries ----
    acc0.x += __shfl_xor_sync(0xffffffffu, acc0.x, 8);
    acc0.y += __shfl_xor_sync(0xffffffffu, acc0.y, 8);
    acc0.z += __shfl_xor_sync(0xffffffffu, acc0.z, 8);
    acc0.w += __shfl_xor_sync(0xffffffffu, acc0.w, 8);
    acc0.x += __shfl_xor_sync(0xffffffffu, acc0.x, 16);
    acc0.y += __shfl_xor_sync(0xffffffffu, acc0.y, 16);
    acc0.z += __shfl_xor_sync(0xffffffffu, acc0.z, 16);
    acc0.w += __shfl_xor_sync(0xffffffffu, acc0.w, 16);

    acc1.x += __shfl_xor_sync(0xffffffffu, acc1.x, 8);
    acc1.y += __shfl_xor_sync(0xffffffffu, acc1.y, 8);
    acc1.z += __shfl_xor_sync(0xffffffffu, acc1.z, 8);
    acc1.w += __shfl_xor_sync(0xffffffffu, acc1.w, 8);
    acc1.x += __shfl_xor_sync(0xffffffffu, acc1.x, 16);
    acc1.y += __shfl_xor_sync(0xffffffffu, acc1.y, 16);
    acc1.z += __shfl_xor_sync(0xffffffffu, acc1.z, 16);
    acc1.w += __shfl_xor_sync(0xffffffffu, acc1.w, 16);

    if (group == 0) {
        *(float4*)(out + (size_t)qbh0 * CH + sub * 4) = acc0;
        if (q1ok)
            *(float4*)(out + (size_t)qbh1 * CH + sub * 4) = acc1;
    }
}

extern "C" void kernel_launch(void* const* d_in, const int* in_sizes, int n_in,
                              void* d_out, int out_size)
{
    const float* value = (const float*)d_in[0];
    const float* loc   = (const float*)d_in[3];
    const float* attw  = (const float*)d_in[4];
    float* out = (float*)d_out;

    dim3 grid((QTOT + 15) / 16, 2 * HD, 1);   // 16 queries per block (2 per warp)
    msda_kernel<<<grid, 256>>>(value, loc, attw, out);
}

// round 17
// speedup vs baseline: 1.2172x; 1.1379x over previous
#include <cuda_runtime.h>
#include <cuda_fp16.h>
#include <cstdint>

// MSDeformAttn on GB300 (sm_103a) — fp16 transposed value + x-pair gather
//   B=2, Hd=8, C=32, P=4, levels=4
//   SHAPES = [(100,150),(50,75),(25,38),(13,19)], L = Q = 19947
//
// All f32 designs plateaued at 137-160us moving 2.6GB of gather lines. This
// version shrinks the work: a pre-pass converts value to fp16 in a scratch
// buffer transposed to [B, Hd, L, C] (contiguous per (b,h), 64B rows). The
// two x-corners of a bilinear sample are then ADJACENT 64B rows, so ONE 128B
// pair-load (16 lanes x 8B) fetches both: 2 loads per point instead of 4,
// half the gather bytes. Boundary cases are folded into per-position weights
// (wlo, whi) computed in the staged setup (reference clip+mask semantics).
// Accumulation is f32; fp16 value rounding keeps rel_err ~3-5e-4 < 1e-3.

#define QTOT 19947
#define LTOT 19947
#define HD   8
#define CH   32

__device__ __half g_vh[(size_t)2 * HD * LTOT * CH + 64];   // [B][Hd][L][C] fp16 (+pad)

// ---- pre-pass: convert + transpose value ----
__global__ void __launch_bounds__(256)
convert_kernel(const float* __restrict__ v)
{
    const int i = blockIdx.x * 256 + threadIdx.x;     // quad index (4 channels)
    const int NQ = 2 * LTOT * HD * CH / 4;            // 2,553,216
    if (i >= NQ) return;

    const int c4 = i & 7;                 // channel quad
    const int h  = (i >> 3) & 7;
    const int bp = i >> 6;                // b*L + pos
    const int pos = bp % LTOT;
    const int b   = bp / LTOT;

    const float4 f = ((const float4*)v)[i];           // coalesced read
    __half2 lo = __floats2half2_rn(f.x, f.y);
    __half2 hi = __floats2half2_rn(f.z, f.w);

    const size_t dq = (((size_t)(b * HD + h) * LTOT + pos) * 8 + c4);
    __half2* dst = (__half2*)g_vh + dq * 2;
    dst[0] = lo;
    dst[1] = hi;
}

// ---- main gather kernel ----
__global__ void __launch_bounds__(256, 7)
msda_kernel(const float* __restrict__ loc,
            const float* __restrict__ attw,
            float* __restrict__ out)
{
    __shared__ float4 sw[8][16];   // [warp][l*4+p] = (wy0*wlo, wy0*whi, wy1*wlo, wy1*whi)
    __shared__ int2   sr[8][16];   // [warp][l*4+p] = (pos_top, pos_bot) pair-start positions

    const int warp = threadIdx.x >> 5;
    const int lane = threadIdx.x & 31;
    const int q = blockIdx.x * 8 + warp;
    if (q >= QTOT) return;                 // uniform across warp

    const int bh = blockIdx.y;             // b*8 + h
    const int b  = bh >> 3;
    const int h  = bh & 7;
    const int qbh = (b * QTOT + q) * HD + h;

    // ---- phase 1: lanes 0-15 compute one (level,point) each ----
    if (lane < 16) {
        const int l = lane >> 2;
        const int Hh = (l == 0) ? 100 : (l == 1) ? 50 : (l == 2) ? 25 : 13;
        const int Ww = (l == 0) ? 150 : (l == 1) ? 75 : (l == 2) ? 38 : 19;
        const int S  = (l == 0) ? 0   : (l == 1) ? 15000 : (l == 2) ? 18750 : 19700;

        const float2 xy = ((const float2*)loc)[(size_t)qbh * 16 + lane]; // coalesced 128B
        const float  wt = attw[(size_t)qbh * 16 + lane];                 // coalesced 64B

        const float x = xy.x * (float)Ww - 0.5f;
        const float y = xy.y * (float)Hh - 0.5f;
        const float xf = floorf(x);
        const float yf = floorf(y);
        const float dx = x - xf;
        const float dy = y - yf;
        const int x0 = (int)xf;            // in [-1, Ww-1]
        const int y0 = (int)yf;            // in [-1, Hh-1]

        // y validity folded into row weights
        const float fy0 = ((unsigned)y0       < (unsigned)Hh) ? 1.f : 0.f;
        const float fy1 = ((unsigned)(y0 + 1) < (unsigned)Hh) ? 1.f : 0.f;
        const float wy0 = wt * (1.f - dy) * fy0;
        const float wy1 = wt * dy * fy1;

        // x pair: load positions (xs, xs+1); weights per loaded position.
        //   x0 in [0,Ww-2] : xs=x0   -> (1-dx, dx)
        //   x0 = -1        : xs=0    -> (dx, 0)      (pos0 is corner x1)
        //   x0 = Ww-1      : xs=Ww-2 -> (0, 1-dx)    (pos xs+1 is corner x0)
        const int xs = min(max(x0, 0), Ww - 2);
        const float wlo = (xs == x0) ? (1.f - dx) : ((xs == x0 + 1) ? dx : 0.f);
        const float whi = (xs == x0) ? dx : ((xs + 1 == x0) ? (1.f - dx) : 0.f);

        const int y0c = max(y0, 0);
        const int y1c = min(y0 + 1, Hh - 1);

        sw[warp][lane] = make_float4(wy0 * wlo, wy0 * whi, wy1 * wlo, wy1 * whi);
        sr[warp][lane] = make_int2(S + y0c * Ww + xs, S + y1c * Ww + xs);
    }
    __syncwarp();

    // ---- phase 2: pair-load gather; 2 groups x 16 lanes ----
    const int group = lane >> 4;           // group 0 -> points 0-7, group 1 -> 8-15
    const int j     = lane & 15;           // byte offset j*8 within the 128B pair window
    // lane j: x-half = j>>3, channels 4*(j&7) .. +3 (as 2 half2)

    const uint2* base = (const uint2*)(g_vh + ((size_t)(b * HD + h) * LTOT) * CH) + j;

    float4 acc = make_float4(0.f, 0.f, 0.f, 0.f);

#pragma unroll
    for (int pp = 0; pp < 8; pp += 2) {
        const int i0 = group * 8 + pp;
        const int i1 = i0 + 1;

        const int2 r0 = sr[warp][i0];      // broadcast LDS.64
        const int2 r1 = sr[warp][i1];

        // 4 independent pair-loads back-to-back (each: one 128B line-window)
        const uint2 t0 = base[r0.x * 8];   // point i0, top row pair
        const uint2 b0 = base[r0.y * 8];   // point i0, bottom row pair
        const uint2 t1 = base[r1.x * 8];
        const uint2 b1 = base[r1.y * 8];

        const float4 w0 = sw[warp][i0];    // broadcast LDS.128
        const float4 w1 = sw[warp][i1];

        const float wt0 = (j < 8) ? w0.x : w0.y;
        const float wb0 = (j < 8) ? w0.z : w0.w;
        const float wt1 = (j < 8) ? w1.x : w1.y;
        const float wb1 = (j < 8) ? w1.z : w1.w;

        float2 f;
        f = __half22float2(*(const __half2*)&t0.x); acc.x += wt0 * f.x; acc.y += wt0 * f.y;
        f = __half22float2(*(const __half2*)&t0.y); acc.z += wt0 * f.x; acc.w += wt0 * f.y;
        f = __half22float2(*(const __half2*)&b0.x); acc.x += wb0 * f.x; acc.y += wb0 * f.y;
        f = __half22float2(*(const __half2*)&b0.y); acc.z += wb0 * f.x; acc.w += wb0 * f.y;
        f = __half22float2(*(const __half2*)&t1.x); acc.x += wt1 * f.x; acc.y += wt1 * f.y;
        f = __half22float2(*(const __half2*)&t1.y); acc.z += wt1 * f.x; acc.w += wt1 * f.y;
        f = __half22float2(*(const __half2*)&b1.x); acc.x += wb1 * f.x; acc.y += wb1 * f.y;
        f = __half22float2(*(const __half2*)&b1.y); acc.z += wb1 * f.x; acc.w += wb1 * f.y;
    }

    // ---- reduce: xor 8 combines the two x-halves (same channels),
    //      xor 16 combines the two point-groups ----
    acc.x += __shfl_xor_sync(0xffffffffu, acc.x, 8);
    acc.y += __shfl_xor_sync(0xffffffffu, acc.y, 8);
    acc.z += __shfl_xor_sync(0xffffffffu, acc.z, 8);
    acc.w += __shfl_xor_sync(0xffffffffu, acc.w, 8);
    acc.x += __shfl_xor_sync(0xffffffffu, acc.x, 16);
    acc.y += __shfl_xor_sync(0xffffffffu, acc.y, 16);
    acc.z += __shfl_xor_sync(0xffffffffu, acc.z, 16);
    acc.w += __shfl_xor_sync(0xffffffffu, acc.w, 16);

    if (lane < 8) {
        // lane j holds channels 4j..4j+3 : 8 lanes x 16B = one 128B store
        *(float4*)(out + (size_t)qbh * CH + lane * 4) = acc;
    }
}

extern "C" void kernel_launch(void* const* d_in, const int* in_sizes, int n_in,
                              void* d_out, int out_size)
{
    const float* value = (const float*)d_in[0];
    const float* loc   = (const float*)d_in[3];
    const float* attw  = (const float*)d_in[4];
    float* out = (float*)d_out;

    const int NQ = 2 * LTOT * HD * CH / 4;
    convert_kernel<<<(NQ + 255) / 256, 256>>>(value);

    dim3 grid((QTOT + 7) / 8, 2 * HD, 1);
    msda_kernel<<<grid, 256>>>(loc, attw, out);
}